// round 10
// baseline (speedup 1.0000x reference)
#include <cuda_runtime.h>

// NeighborhoodAggregation: fused persistent preprocessing (zero+rank+scan+scatter
// with software grid barriers) + warp-per-node register-reduction aggregation.
// out = (Z[node] + sum_{e: dst=node} Z[src_e]) / (deg(node)+1)
// Inputs: Z_real (100000*64 f32), Z_imag (100000*64 f32), edge_index (2*1600000 int32)
// Output: float32 [A_real ; A_imag]

#define MAX_NODES 100352
#define MAX_EDGES 1600000
#define MAX_BLOCKS 256
#define PRE_THREADS 1024

__device__ int g_counts[MAX_NODES];        // in-degree (edges only)
__device__ int g_offsets[MAX_NODES];       // exclusive prefix of counts
__device__ int g_rank[MAX_EDGES];          // rank of edge within its dst bucket
__device__ int g_sorted[MAX_EDGES];        // src indices grouped by dst
__device__ int g_partial[MAX_BLOCKS];      // per-block degree sums
__device__ unsigned g_bar_count = 0;       // software grid barrier state
__device__ unsigned g_bar_gen = 0;         // (self-restoring across graph replays)

// Software grid barrier. Requires all blocks co-resident (grid = #SMs, 1 block/SM).
__device__ __forceinline__ void grid_barrier(int nblocks)
{
    __syncthreads();
    if (threadIdx.x == 0) {
        __threadfence();                                   // release my phase's writes
        unsigned my_gen = atomicAdd(&g_bar_gen, 0u);       // read gen BEFORE arriving
        __threadfence();                                   // order gen-read before arrive
        unsigned arrived = atomicAdd(&g_bar_count, 1u);
        if (arrived == (unsigned)nblocks - 1u) {
            g_bar_count = 0;                               // reset for next barrier
            __threadfence();                               // reset visible before gen bump
            atomicAdd(&g_bar_gen, 1u);                     // release
        } else {
            while (atomicAdd(&g_bar_gen, 0u) == my_gen) { }
        }
        __threadfence();                                   // acquire other blocks' writes
    }
    __syncthreads();
}

// ---- Fused preprocessing: zero -> rank -> scan -> scatter ----
__global__ void __launch_bounds__(PRE_THREADS, 1)
preprocess_kernel(const int* __restrict__ src,
                  const int* __restrict__ dst,
                  int n_nodes, int n_edges, int nblocks)
{
    const int tid = blockIdx.x * PRE_THREADS + threadIdx.x;
    const int nthreads = nblocks * PRE_THREADS;

    // ---- P0: zero counts ----
    for (int i = tid; i < n_nodes; i += nthreads) g_counts[i] = 0;
    grid_barrier(nblocks);

    // ---- P1: histogram of dst, capturing per-edge rank ----
    // Stride-separated lanes: at each step, a warp touches 32 consecutive edges.
    for (int i = tid; i < n_edges; i += nthreads) {
        g_rank[i] = atomicAdd(&g_counts[dst[i]], 1);
    }
    grid_barrier(nblocks);

    // ---- P2: per-block partial sum of counts over this block's node chunk ----
    const int chunk = (n_nodes + nblocks - 1) / nblocks;   // <= 1024 for >=98 blocks
    const int start = blockIdx.x * chunk;
    int end = start + chunk; if (end > n_nodes) end = n_nodes;

    __shared__ int s_scan[PRE_THREADS];
    {
        int s = 0;
        for (int i = start + threadIdx.x; i < end; i += PRE_THREADS) s += g_counts[i];
        s_scan[threadIdx.x] = s;
        __syncthreads();
        for (int off = PRE_THREADS / 2; off > 0; off >>= 1) {
            if (threadIdx.x < off) s_scan[threadIdx.x] += s_scan[threadIdx.x + off];
            __syncthreads();
        }
        if (threadIdx.x == 0) g_partial[blockIdx.x] = s_scan[0];
    }
    grid_barrier(nblocks);

    // ---- P3: block base = sum of partials below; block-local scan; write offsets ----
    {
        __shared__ int s_base;
        if (threadIdx.x == 0) {
            int b = 0;
            for (int j = 0; j < blockIdx.x; j++) b += g_partial[j];
            s_base = b;
        }
        int t = threadIdx.x;
        int i = start + t;
        int c = (t < chunk && i < n_nodes) ? g_counts[i] : 0;
        s_scan[t] = c;
        __syncthreads();
        // Hillis-Steele inclusive scan over 1024 entries
        for (int off = 1; off < PRE_THREADS; off <<= 1) {
            int v = (t >= off) ? s_scan[t - off] : 0;
            __syncthreads();
            s_scan[t] += v;
            __syncthreads();
        }
        if (t < chunk && i < n_nodes) {
            g_offsets[i] = s_base + s_scan[t] - c;         // exclusive
        }
    }
    grid_barrier(nblocks);

    // ---- P4: atomic-free scatter: pos = offsets[dst] + rank ----
    for (int i = tid; i < n_edges; i += nthreads) {
        g_sorted[g_offsets[dst[i]] + g_rank[i]] = src[i];
    }
}

// ---- Aggregation: warp-per-node register reduction ----
// Lane l: l<16 -> real chunk l, l>=16 -> imag chunk l-16.
// Per edge, the full warp reads one 1KB row (512B real + 512B imag), coalesced.
__global__ void agg_kernel(const float4* __restrict__ zr,
                           const float4* __restrict__ zi,
                           float4* __restrict__ outr,
                           float4* __restrict__ outi,
                           int n_nodes)
{
    int warp_in_block = threadIdx.x >> 5;
    int node = blockIdx.x * (blockDim.x >> 5) + warp_in_block;
    if (node >= n_nodes) return;
    int lane = threadIdx.x & 31;

    const float4* __restrict__ zbase = (lane < 16) ? zr : zi;
    int chunk = lane & 15;

    // self-loop contribution
    float4 acc = zbase[(size_t)node * 16 + chunk];

    int base = g_offsets[node];
    int cnt = g_counts[node];
    const int* __restrict__ idx = g_sorted + base;

    int k = 0;
    for (; k + 8 <= cnt; k += 8) {
        int s0 = idx[k + 0];
        int s1 = idx[k + 1];
        int s2 = idx[k + 2];
        int s3 = idx[k + 3];
        int s4 = idx[k + 4];
        int s5 = idx[k + 5];
        int s6 = idx[k + 6];
        int s7 = idx[k + 7];
        float4 v0 = zbase[(size_t)s0 * 16 + chunk];
        float4 v1 = zbase[(size_t)s1 * 16 + chunk];
        float4 v2 = zbase[(size_t)s2 * 16 + chunk];
        float4 v3 = zbase[(size_t)s3 * 16 + chunk];
        float4 v4 = zbase[(size_t)s4 * 16 + chunk];
        float4 v5 = zbase[(size_t)s5 * 16 + chunk];
        float4 v6 = zbase[(size_t)s6 * 16 + chunk];
        float4 v7 = zbase[(size_t)s7 * 16 + chunk];
        acc.x += ((v0.x + v1.x) + (v2.x + v3.x)) + ((v4.x + v5.x) + (v6.x + v7.x));
        acc.y += ((v0.y + v1.y) + (v2.y + v3.y)) + ((v4.y + v5.y) + (v6.y + v7.y));
        acc.z += ((v0.z + v1.z) + (v2.z + v3.z)) + ((v4.z + v5.z) + (v6.z + v7.z));
        acc.w += ((v0.w + v1.w) + (v2.w + v3.w)) + ((v4.w + v5.w) + (v6.w + v7.w));
    }
    for (; k + 2 <= cnt; k += 2) {
        int s0 = idx[k + 0];
        int s1 = idx[k + 1];
        float4 v0 = zbase[(size_t)s0 * 16 + chunk];
        float4 v1 = zbase[(size_t)s1 * 16 + chunk];
        acc.x += v0.x + v1.x;
        acc.y += v0.y + v1.y;
        acc.z += v0.z + v1.z;
        acc.w += v0.w + v1.w;
    }
    if (k < cnt) {
        int s0 = idx[k];
        float4 v0 = zbase[(size_t)s0 * 16 + chunk];
        acc.x += v0.x; acc.y += v0.y; acc.z += v0.z; acc.w += v0.w;
    }

    float inv = 1.0f / (float)(cnt + 1);
    acc.x *= inv; acc.y *= inv; acc.z *= inv; acc.w *= inv;

    float4* __restrict__ obase = (lane < 16) ? outr : outi;
    obase[(size_t)node * 16 + chunk] = acc;
}

extern "C" void kernel_launch(void* const* d_in, const int* in_sizes, int n_in,
                              void* d_out, int out_size)
{
    const float* Z_real = (const float*)d_in[0];
    const float* Z_imag = (const float*)d_in[1];
    const int* edge_index = (const int*)d_in[2];

    int n_nodes = in_sizes[0] / 64;
    int n_edges = in_sizes[2] / 2;

    const int* src = edge_index;
    const int* dst = edge_index + n_edges;

    float* out_real = (float*)d_out;
    float* out_imag = (float*)d_out + (size_t)n_nodes * 64;

    // One block per SM so the software grid barrier cannot deadlock.
    static int smCount = 0;
    if (smCount == 0) {
        cudaDeviceGetAttribute(&smCount, cudaDevAttrMultiProcessorCount, 0);
        if (smCount <= 0) smCount = 148;
        if (smCount > MAX_BLOCKS) smCount = MAX_BLOCKS;
    }
    int nblocks = smCount;

    preprocess_kernel<<<nblocks, PRE_THREADS>>>(src, dst, n_nodes, n_edges, nblocks);

    {
        int threads = 256;
        int warps_per_block = threads / 32;  // 8 nodes per block
        int blocks = (n_nodes + warps_per_block - 1) / warps_per_block;
        agg_kernel<<<blocks, threads>>>((const float4*)Z_real, (const float4*)Z_imag,
                                        (float4*)out_real, (float4*)out_imag, n_nodes);
    }
}